// round 8
// baseline (speedup 1.0000x reference)
#include <cuda_runtime.h>
#include <cstdint>

#define NN 100000
#define EP 1000000
#define EN 500000
#define NBLK ((NN + 1023) / 1024)   // 98

// ---------------- scratch (device globals: no allocations allowed) ----------
__device__ __align__(256) float g_aggA[NN * 64];   // pos-sourced aggregation sums
__device__ __align__(256) float g_aggB[NN * 64];   // neg-sourced aggregation sums
__device__ __align__(256) float g_z[NN * 64];      // layer1 output
__device__ __align__(256) float g_dpos[NN];        // sum of pos weights per dst
__device__ __align__(256) float g_dneg[NN];        // sum of neg weights per dst
// CSR build
__device__ __align__(256) int  g_pcnt[NN];
__device__ __align__(256) int  g_ncnt[NN];
__device__ __align__(256) int  g_poff[NN + 1];
__device__ __align__(256) int  g_noff[NN + 1];
__device__ __align__(256) int  g_prank[EP];
__device__ __align__(256) int  g_nrank[EN];
__device__ __align__(256) int  g_blksum[2][NBLK];
__device__ __align__(256) int2 g_pedge[EP];        // (src, bitcast weight) in dst order
__device__ __align__(256) int2 g_nedge[EN];

// ---------------- helpers ----------------------------------------------------
__device__ __forceinline__ float tanha(float x) {
    float r;
    asm("tanh.approx.f32 %0, %1;" : "=f"(r) : "f"(x));
    return r;
}

// ---------------- CSR build --------------------------------------------------
__global__ void zero_cnt_kernel() {
    int i = blockIdx.x * blockDim.x + threadIdx.x;
    if (i < NN) {
        g_pcnt[i] = 0;
        g_ncnt[i] = 0;
        g_dpos[i] = 0.f;
        g_dneg[i] = 0.f;
    }
}

// Count edges per dst; the atomic's return value is this edge's rank within dst.
__global__ void hist_kernel(const int* __restrict__ pei, const int* __restrict__ nei,
                            const float* __restrict__ pw, const float* __restrict__ nw) {
    int t = blockIdx.x * blockDim.x + threadIdx.x;
    if (t < EP) {
        int d = pei[EP + t];
        g_prank[t] = atomicAdd(&g_pcnt[d], 1);
        atomicAdd(&g_dpos[d], pw[t]);
    } else if (t < EP + EN) {
        int e = t - EP;
        int d = nei[EN + e];
        g_nrank[e] = atomicAdd(&g_ncnt[d], 1);
        atomicAdd(&g_dneg[d], nw[e]);
    }
}

// Phase 1: per-block exclusive scan; block totals to g_blksum.
__global__ void scan1_kernel() {
    __shared__ int swsum[32];
    int arr = blockIdx.y;
    const int* cnt = arr ? g_ncnt : g_pcnt;
    int* off = arr ? g_noff : g_poff;
    int tid = threadIdx.x, lane = tid & 31, wid = tid >> 5;
    int i = blockIdx.x * 1024 + tid;
    int v = (i < NN) ? cnt[i] : 0;
    int val = v;
#pragma unroll
    for (int o = 1; o < 32; o <<= 1) {
        int t2 = __shfl_up_sync(0xFFFFFFFFu, val, o);
        if (lane >= o) val += t2;
    }
    if (lane == 31) swsum[wid] = val;
    __syncthreads();
    if (wid == 0) {
        int s = swsum[lane];
#pragma unroll
        for (int o = 1; o < 32; o <<= 1) {
            int t2 = __shfl_up_sync(0xFFFFFFFFu, s, o);
            if (lane >= o) s += t2;
        }
        swsum[lane] = s;
    }
    __syncthreads();
    int woff = wid ? swsum[wid - 1] : 0;
    int incl = val + woff;
    if (i < NN) off[i] = incl - v;
    if (tid == 1023) g_blksum[arr][blockIdx.x] = incl;
}

// Phase 2 (merged): each block reduces blksum[0..bx-1] and adds it.
__global__ void scan3_kernel() {
    __shared__ int s_pref;
    int arr = blockIdx.y;
    int* off = arr ? g_noff : g_poff;
    int bx = blockIdx.x;
    if (threadIdx.x < 32) {
        int lane = threadIdx.x;
        int acc = 0;
        for (int idx = lane; idx < bx; idx += 32) acc += g_blksum[arr][idx];
#pragma unroll
        for (int o = 16; o; o >>= 1) acc += __shfl_xor_sync(0xFFFFFFFFu, acc, o);
        if (lane == 0) s_pref = acc;
    }
    __syncthreads();
    int pref = s_pref;
    int i = bx * 1024 + threadIdx.x;
    if (i < NN) off[i] += pref;
    if (bx == NBLK - 1 && threadIdx.x == 0)
        off[NN] = pref + g_blksum[arr][NBLK - 1];
}

// Fill CSR edge arrays — no atomics (slot = off[dst] + precomputed rank).
__global__ void fill_kernel(const int* __restrict__ pei, const int* __restrict__ nei,
                            const float* __restrict__ pw, const float* __restrict__ nw) {
    int t = blockIdx.x * blockDim.x + threadIdx.x;
    if (t < EP) {
        int dst = pei[EP + t];
        g_pedge[g_poff[dst] + g_prank[t]] = make_int2(pei[t], __float_as_int(pw[t]));
    } else if (t < EP + EN) {
        int e = t - EP;
        int dst = nei[EN + e];
        g_nedge[g_noff[dst] + g_nrank[e]] = make_int2(nei[e], __float_as_int(nw[e]));
    }
}

// ---------------- CSR gather (pos + neg in one pass, 4-deep pipelined) -------
// 16 threads per node; thread c owns float4 chunk c of the 64-float row.
__global__ void gather_kernel(const float4* __restrict__ xfeat, int use_z, int swap) {
    int t = blockIdx.x * blockDim.x + threadIdx.x;
    int n = t >> 4;
    if (n >= NN) return;
    int c = t & 15;
    const float4* feat = use_z ? reinterpret_cast<const float4*>(g_z) : xfeat;

    float4 accA = make_float4(0.f, 0.f, 0.f, 0.f);
    {
        int b = g_poff[n], e = g_poff[n + 1];
        int i = b;
        for (; i + 4 <= e; i += 4) {
            int2 e0 = g_pedge[i + 0];
            int2 e1 = g_pedge[i + 1];
            int2 e2 = g_pedge[i + 2];
            int2 e3 = g_pedge[i + 3];
            float4 v0 = __ldg(&feat[(size_t)e0.x * 16 + c]);
            float4 v1 = __ldg(&feat[(size_t)e1.x * 16 + c]);
            float4 v2 = __ldg(&feat[(size_t)e2.x * 16 + c]);
            float4 v3 = __ldg(&feat[(size_t)e3.x * 16 + c]);
            float w0 = __int_as_float(e0.y), w1 = __int_as_float(e1.y);
            float w2 = __int_as_float(e2.y), w3 = __int_as_float(e3.y);
            accA.x += w0 * v0.x + w1 * v1.x + w2 * v2.x + w3 * v3.x;
            accA.y += w0 * v0.y + w1 * v1.y + w2 * v2.y + w3 * v3.y;
            accA.z += w0 * v0.z + w1 * v1.z + w2 * v2.z + w3 * v3.z;
            accA.w += w0 * v0.w + w1 * v1.w + w2 * v2.w + w3 * v3.w;
        }
        for (; i < e; i++) {
            int2 ed = g_pedge[i];
            float w = __int_as_float(ed.y);
            float4 v = __ldg(&feat[(size_t)ed.x * 16 + c]);
            accA.x += w * v.x; accA.y += w * v.y; accA.z += w * v.z; accA.w += w * v.w;
        }
    }

    int sc = c ^ (swap << 3);
    float4 accB = make_float4(0.f, 0.f, 0.f, 0.f);
    {
        int b = g_noff[n], e = g_noff[n + 1];
        int i = b;
        for (; i + 4 <= e; i += 4) {
            int2 e0 = g_nedge[i + 0];
            int2 e1 = g_nedge[i + 1];
            int2 e2 = g_nedge[i + 2];
            int2 e3 = g_nedge[i + 3];
            float4 v0 = __ldg(&feat[(size_t)e0.x * 16 + sc]);
            float4 v1 = __ldg(&feat[(size_t)e1.x * 16 + sc]);
            float4 v2 = __ldg(&feat[(size_t)e2.x * 16 + sc]);
            float4 v3 = __ldg(&feat[(size_t)e3.x * 16 + sc]);
            float w0 = __int_as_float(e0.y), w1 = __int_as_float(e1.y);
            float w2 = __int_as_float(e2.y), w3 = __int_as_float(e3.y);
            accB.x += w0 * v0.x + w1 * v1.x + w2 * v2.x + w3 * v3.x;
            accB.y += w0 * v0.y + w1 * v1.y + w2 * v2.y + w3 * v3.y;
            accB.z += w0 * v0.z + w1 * v1.z + w2 * v2.z + w3 * v3.z;
            accB.w += w0 * v0.w + w1 * v1.w + w2 * v2.w + w3 * v3.w;
        }
        for (; i < e; i++) {
            int2 ed = g_nedge[i];
            float w = __int_as_float(ed.y);
            float4 v = __ldg(&feat[(size_t)ed.x * 16 + sc]);
            accB.x += w * v.x; accB.y += w * v.y; accB.z += w * v.z; accB.w += w * v.w;
        }
    }

    reinterpret_cast<float4*>(g_aggA)[n * 16 + c] = accA;
    reinterpret_cast<float4*>(g_aggB)[n * 16 + c] = accB;
}

// ---------------- layer 1: z = tanh([ap,x]@w1p+b1p | [an,x]@w1n+b1n) ---------
__global__ __launch_bounds__(128) void layer1_kernel(
    const float4* __restrict__ x4,
    const float* __restrict__ w1p, const float* __restrict__ b1p,
    const float* __restrict__ w1n, const float* __restrict__ b1n) {
    __shared__ float sWp[128 * 32];
    __shared__ float sWn[128 * 32];
    for (int i = threadIdx.x; i < 128 * 32; i += 128) {
        sWp[i] = w1p[i];
        sWn[i] = w1n[i];
    }
    __syncthreads();

    int n = blockIdx.x * 128 + threadIdx.x;
    if (n >= NN) return;

    float invp = 1.f / fmaxf(g_dpos[n], 1e-12f);
    float invn = 1.f / fmaxf(g_dneg[n], 1e-12f);

    float aP[32], aN[32];
#pragma unroll
    for (int j = 0; j < 32; j++) { aP[j] = b1p[j]; aN[j] = b1n[j]; }

    const float4* rA = reinterpret_cast<const float4*>(g_aggA) + n * 16;
    const float4* rB = reinterpret_cast<const float4*>(g_aggB) + n * 16;
    const float4* rX = x4 + n * 16;

#pragma unroll 1
    for (int k4 = 0; k4 < 16; k4++) {
        float4 a = rA[k4];
        float4 b = rB[k4];
        float4 xv = rX[k4];
        float av[4] = { a.x * invp, a.y * invp, a.z * invp, a.w * invp };
        float bv[4] = { b.x * invn, b.y * invn, b.z * invn, b.w * invn };
        float xe[4] = { xv.x, xv.y, xv.z, xv.w };
#pragma unroll
        for (int kk = 0; kk < 4; kk++) {
            int k = k4 * 4 + kk;
            const float4* wpA = reinterpret_cast<const float4*>(sWp + k * 32);
            const float4* wpX = reinterpret_cast<const float4*>(sWp + (64 + k) * 32);
            const float4* wnA = reinterpret_cast<const float4*>(sWn + k * 32);
            const float4* wnX = reinterpret_cast<const float4*>(sWn + (64 + k) * 32);
#pragma unroll
            for (int j4 = 0; j4 < 8; j4++) {
                float4 wp = wpA[j4];
                float4 wx = wpX[j4];
                float4 wn = wnA[j4];
                float4 wq = wnX[j4];
                aP[4 * j4 + 0] += av[kk] * wp.x + xe[kk] * wx.x;
                aP[4 * j4 + 1] += av[kk] * wp.y + xe[kk] * wx.y;
                aP[4 * j4 + 2] += av[kk] * wp.z + xe[kk] * wx.z;
                aP[4 * j4 + 3] += av[kk] * wp.w + xe[kk] * wx.w;
                aN[4 * j4 + 0] += bv[kk] * wn.x + xe[kk] * wq.x;
                aN[4 * j4 + 1] += bv[kk] * wn.y + xe[kk] * wq.y;
                aN[4 * j4 + 2] += bv[kk] * wn.z + xe[kk] * wq.z;
                aN[4 * j4 + 3] += bv[kk] * wn.w + xe[kk] * wq.w;
            }
        }
    }

    float4* zr = reinterpret_cast<float4*>(g_z + (size_t)n * 64);
#pragma unroll
    for (int j4 = 0; j4 < 8; j4++) {
        zr[j4] = make_float4(tanha(aP[4 * j4 + 0]), tanha(aP[4 * j4 + 1]),
                             tanha(aP[4 * j4 + 2]), tanha(aP[4 * j4 + 3]));
        zr[8 + j4] = make_float4(tanha(aN[4 * j4 + 0]), tanha(aN[4 * j4 + 1]),
                                 tanha(aN[4 * j4 + 2]), tanha(aN[4 * j4 + 3]));
    }
}

// ---------------- fused layer 2 + layer 3 ------------------------------------
// z2 = tanh([A1,A2,zp]@w2p+b2p | [A3,A4,zn]@w2n+b2n)  kept in registers,
// then out = tanh(z2 @ wout + bout) computed in two 32-wide halves to cap
// live registers at ~96 floats.
__global__ __launch_bounds__(128) void layer23_kernel(
    const float* __restrict__ w2p, const float* __restrict__ b2p,
    const float* __restrict__ w2n, const float* __restrict__ b2n,
    const float* __restrict__ wout, const float* __restrict__ bout,
    float* __restrict__ out) {
    __shared__ float sP[96 * 32];
    __shared__ float sN[96 * 32];
    __shared__ float sO[64 * 64];
    for (int i = threadIdx.x; i < 96 * 32; i += 128) {
        sP[i] = w2p[i];
        sN[i] = w2n[i];
    }
    for (int i = threadIdx.x; i < 64 * 64; i += 128) sO[i] = wout[i];
    __syncthreads();

    int n = blockIdx.x * 128 + threadIdx.x;
    if (n >= NN) return;

    float invp = 1.f / fmaxf(g_dpos[n], 1e-12f);
    float invn = 1.f / fmaxf(g_dneg[n], 1e-12f);

    float aP[32], aN[32];
#pragma unroll
    for (int j = 0; j < 32; j++) { aP[j] = b2p[j]; aN[j] = b2n[j]; }

    const float4* rA = reinterpret_cast<const float4*>(g_aggA) + n * 16;
    const float4* rB = reinterpret_cast<const float4*>(g_aggB) + n * 16;
    const float4* rZ = reinterpret_cast<const float4*>(g_z) + n * 16;

#pragma unroll 1
    for (int k4 = 0; k4 < 8; k4++) {
        float4 A1 = rA[k4];
        float4 A3 = rA[8 + k4];
        float4 A2 = rB[k4];
        float4 A4 = rB[8 + k4];
        float4 zp = rZ[k4];
        float4 zn = rZ[8 + k4];
        float a1[4] = { A1.x * invp, A1.y * invp, A1.z * invp, A1.w * invp };
        float a3[4] = { A3.x * invp, A3.y * invp, A3.z * invp, A3.w * invp };
        float a2[4] = { A2.x * invn, A2.y * invn, A2.z * invn, A2.w * invn };
        float a4[4] = { A4.x * invn, A4.y * invn, A4.z * invn, A4.w * invn };
        float zpv[4] = { zp.x, zp.y, zp.z, zp.w };
        float znv[4] = { zn.x, zn.y, zn.z, zn.w };
#pragma unroll
        for (int kk = 0; kk < 4; kk++) {
            int k = k4 * 4 + kk;
            const float4* p0 = reinterpret_cast<const float4*>(sP + k * 32);
            const float4* p1 = reinterpret_cast<const float4*>(sP + (32 + k) * 32);
            const float4* p2 = reinterpret_cast<const float4*>(sP + (64 + k) * 32);
            const float4* q0 = reinterpret_cast<const float4*>(sN + k * 32);
            const float4* q1 = reinterpret_cast<const float4*>(sN + (32 + k) * 32);
            const float4* q2 = reinterpret_cast<const float4*>(sN + (64 + k) * 32);
#pragma unroll
            for (int j4 = 0; j4 < 8; j4++) {
                float4 w0 = p0[j4], w1 = p1[j4], w2 = p2[j4];
                aP[4 * j4 + 0] += a1[kk] * w0.x + a2[kk] * w1.x + zpv[kk] * w2.x;
                aP[4 * j4 + 1] += a1[kk] * w0.y + a2[kk] * w1.y + zpv[kk] * w2.y;
                aP[4 * j4 + 2] += a1[kk] * w0.z + a2[kk] * w1.z + zpv[kk] * w2.z;
                aP[4 * j4 + 3] += a1[kk] * w0.w + a2[kk] * w1.w + zpv[kk] * w2.w;
                float4 v0 = q0[j4], v1 = q1[j4], v2 = q2[j4];
                aN[4 * j4 + 0] += a3[kk] * v0.x + a4[kk] * v1.x + znv[kk] * v2.x;
                aN[4 * j4 + 1] += a3[kk] * v0.y + a4[kk] * v1.y + znv[kk] * v2.y;
                aN[4 * j4 + 2] += a3[kk] * v0.z + a4[kk] * v1.z + znv[kk] * v2.z;
                aN[4 * j4 + 3] += a3[kk] * v0.w + a4[kk] * v1.w + znv[kk] * v2.w;
            }
        }
    }

    // tanh -> z2 in registers (z2 = [aP | aN])
#pragma unroll
    for (int j = 0; j < 32; j++) { aP[j] = tanha(aP[j]); aN[j] = tanha(aN[j]); }

    // layer 3 in two 32-wide output halves to limit live registers
    float4* orow = reinterpret_cast<float4*>(out + (size_t)n * 64);
#pragma unroll 1
    for (int h = 0; h < 2; h++) {
        float o[32];
#pragma unroll
        for (int j = 0; j < 32; j++) o[j] = bout[h * 32 + j];
#pragma unroll 1
        for (int k4 = 0; k4 < 8; k4++) {
#pragma unroll
            for (int kk = 0; kk < 4; kk++) {
                int k = k4 * 4 + kk;
                float zp = aP[k];
                float zn = aN[k];
                const float4* w0 = reinterpret_cast<const float4*>(sO + k * 64 + h * 32);
                const float4* w1 = reinterpret_cast<const float4*>(sO + (32 + k) * 64 + h * 32);
#pragma unroll
                for (int j4 = 0; j4 < 8; j4++) {
                    float4 a = w0[j4];
                    float4 b = w1[j4];
                    o[4 * j4 + 0] += zp * a.x + zn * b.x;
                    o[4 * j4 + 1] += zp * a.y + zn * b.y;
                    o[4 * j4 + 2] += zp * a.z + zn * b.z;
                    o[4 * j4 + 3] += zp * a.w + zn * b.w;
                }
            }
        }
#pragma unroll
        for (int j4 = 0; j4 < 8; j4++) {
            orow[h * 8 + j4] = make_float4(tanha(o[4 * j4 + 0]), tanha(o[4 * j4 + 1]),
                                           tanha(o[4 * j4 + 2]), tanha(o[4 * j4 + 3]));
        }
    }
}

// ---------------- launch -----------------------------------------------------
extern "C" void kernel_launch(void* const* d_in, const int* in_sizes, int n_in,
                              void* d_out, int out_size) {
    const int*   pei  = (const int*)d_in[0];
    const int*   nei  = (const int*)d_in[1];
    const float* pw   = (const float*)d_in[2];
    const float* nw   = (const float*)d_in[3];
    const float* x    = (const float*)d_in[4];
    const float* w1p  = (const float*)d_in[5];
    const float* b1p  = (const float*)d_in[6];
    const float* w1n  = (const float*)d_in[7];
    const float* b1n  = (const float*)d_in[8];
    const float* w2p  = (const float*)d_in[9];
    const float* b2p  = (const float*)d_in[10];
    const float* w2n  = (const float*)d_in[11];
    const float* b2n  = (const float*)d_in[12];
    const float* wout = (const float*)d_in[13];
    const float* bout = (const float*)d_in[14];
    float* out = (float*)d_out;

    const int EB = (EP + EN + 255) / 256;
    const int GB = (NN * 16 + 255) / 256;
    const int LB = (NN + 127) / 128;

    // CSR build (shared by both layers)
    zero_cnt_kernel<<<(NN + 255) / 256, 256>>>();
    hist_kernel<<<EB, 256>>>(pei, nei, pw, nw);
    scan1_kernel<<<dim3(NBLK, 2), 1024>>>();
    scan3_kernel<<<dim3(NBLK, 2), 1024>>>();
    fill_kernel<<<EB, 256>>>(pei, nei, pw, nw);

    // Layer 1
    gather_kernel<<<GB, 256>>>((const float4*)x, 0, 0);
    layer1_kernel<<<LB, 128>>>((const float4*)x, w1p, b1p, w1n, b1n);

    // Layer 2+3 fused (neg side swaps zp/zn halves in the gather)
    gather_kernel<<<GB, 256>>>((const float4*)x, 1, 1);
    layer23_kernel<<<LB, 128>>>(w2p, b2p, w2n, b2n, wout, bout, out);

    (void)in_sizes; (void)n_in; (void)out_size;
}

// round 9
// speedup vs baseline: 1.1794x; 1.1794x over previous
#include <cuda_runtime.h>
#include <cstdint>

#define NN 100000
#define EP 1000000
#define EN 500000
#define NBLK ((NN + 1023) / 1024)   // 98

// ---------------- scratch (device globals: no allocations allowed) ----------
__device__ __align__(256) float g_aggA[NN * 64];   // pos-sourced aggregation sums
__device__ __align__(256) float g_aggB[NN * 64];   // neg-sourced aggregation sums
__device__ __align__(256) float g_z[NN * 64];      // layer1 output, then layer2 output
__device__ __align__(256) float g_dpos[NN];        // sum of pos weights per dst
__device__ __align__(256) float g_dneg[NN];        // sum of neg weights per dst
// CSR build
__device__ __align__(256) int  g_pcnt[NN];
__device__ __align__(256) int  g_ncnt[NN];
__device__ __align__(256) int  g_poff[NN + 1];
__device__ __align__(256) int  g_noff[NN + 1];
__device__ __align__(256) int  g_prank[EP];
__device__ __align__(256) int  g_nrank[EN];
__device__ __align__(256) int  g_blksum[2][NBLK];
__device__ __align__(256) int2 g_pedge[EP];        // (src, bitcast weight) in dst order
__device__ __align__(256) int2 g_nedge[EN];

// ---------------- helpers ----------------------------------------------------
__device__ __forceinline__ float tanha(float x) {
    float r;
    asm("tanh.approx.f32 %0, %1;" : "=f"(r) : "f"(x));
    return r;
}

// ---------------- CSR build --------------------------------------------------
__global__ void zero_cnt_kernel() {
    int i = blockIdx.x * blockDim.x + threadIdx.x;
    if (i < NN) {
        g_pcnt[i] = 0;
        g_ncnt[i] = 0;
        g_dpos[i] = 0.f;
        g_dneg[i] = 0.f;
    }
}

// Count edges per dst; the atomic's return value is this edge's rank within dst.
__global__ void hist_kernel(const int* __restrict__ pei, const int* __restrict__ nei,
                            const float* __restrict__ pw, const float* __restrict__ nw) {
    int t = blockIdx.x * blockDim.x + threadIdx.x;
    if (t < EP) {
        int d = pei[EP + t];
        g_prank[t] = atomicAdd(&g_pcnt[d], 1);
        atomicAdd(&g_dpos[d], pw[t]);
    } else if (t < EP + EN) {
        int e = t - EP;
        int d = nei[EN + e];
        g_nrank[e] = atomicAdd(&g_ncnt[d], 1);
        atomicAdd(&g_dneg[d], nw[e]);
    }
}

// Phase 1: per-block exclusive scan; block totals to g_blksum.
__global__ void scan1_kernel() {
    __shared__ int swsum[32];
    int arr = blockIdx.y;
    const int* cnt = arr ? g_ncnt : g_pcnt;
    int* off = arr ? g_noff : g_poff;
    int tid = threadIdx.x, lane = tid & 31, wid = tid >> 5;
    int i = blockIdx.x * 1024 + tid;
    int v = (i < NN) ? cnt[i] : 0;
    int val = v;
#pragma unroll
    for (int o = 1; o < 32; o <<= 1) {
        int t2 = __shfl_up_sync(0xFFFFFFFFu, val, o);
        if (lane >= o) val += t2;
    }
    if (lane == 31) swsum[wid] = val;
    __syncthreads();
    if (wid == 0) {
        int s = swsum[lane];
#pragma unroll
        for (int o = 1; o < 32; o <<= 1) {
            int t2 = __shfl_up_sync(0xFFFFFFFFu, s, o);
            if (lane >= o) s += t2;
        }
        swsum[lane] = s;
    }
    __syncthreads();
    int woff = wid ? swsum[wid - 1] : 0;
    int incl = val + woff;
    if (i < NN) off[i] = incl - v;
    if (tid == 1023) g_blksum[arr][blockIdx.x] = incl;
}

// Phase 2 (merged): each block reduces blksum[0..bx-1] and adds it.
__global__ void scan3_kernel() {
    __shared__ int s_pref;
    int arr = blockIdx.y;
    int* off = arr ? g_noff : g_poff;
    int bx = blockIdx.x;
    if (threadIdx.x < 32) {
        int lane = threadIdx.x;
        int acc = 0;
        for (int idx = lane; idx < bx; idx += 32) acc += g_blksum[arr][idx];
#pragma unroll
        for (int o = 16; o; o >>= 1) acc += __shfl_xor_sync(0xFFFFFFFFu, acc, o);
        if (lane == 0) s_pref = acc;
    }
    __syncthreads();
    int pref = s_pref;
    int i = bx * 1024 + threadIdx.x;
    if (i < NN) off[i] += pref;
    if (bx == NBLK - 1 && threadIdx.x == 0)
        off[NN] = pref + g_blksum[arr][NBLK - 1];
}

// Fill CSR edge arrays — no atomics (slot = off[dst] + precomputed rank).
__global__ void fill_kernel(const int* __restrict__ pei, const int* __restrict__ nei,
                            const float* __restrict__ pw, const float* __restrict__ nw) {
    int t = blockIdx.x * blockDim.x + threadIdx.x;
    if (t < EP) {
        int dst = pei[EP + t];
        g_pedge[g_poff[dst] + g_prank[t]] = make_int2(pei[t], __float_as_int(pw[t]));
    } else if (t < EP + EN) {
        int e = t - EP;
        int dst = nei[EN + e];
        g_nedge[g_noff[dst] + g_nrank[e]] = make_int2(nei[e], __float_as_int(nw[e]));
    }
}

// ---------------- CSR gather (pos + neg in one pass, 4-deep pipelined) -------
// 16 threads per node; thread c owns float4 chunk c of the 64-float row.
__global__ void gather_kernel(const float4* __restrict__ xfeat, int use_z, int swap) {
    int t = blockIdx.x * blockDim.x + threadIdx.x;
    int n = t >> 4;
    if (n >= NN) return;
    int c = t & 15;
    const float4* feat = use_z ? reinterpret_cast<const float4*>(g_z) : xfeat;

    float4 accA = make_float4(0.f, 0.f, 0.f, 0.f);
    {
        int b = g_poff[n], e = g_poff[n + 1];
        int i = b;
        for (; i + 4 <= e; i += 4) {
            int2 e0 = g_pedge[i + 0];
            int2 e1 = g_pedge[i + 1];
            int2 e2 = g_pedge[i + 2];
            int2 e3 = g_pedge[i + 3];
            float4 v0 = __ldg(&feat[(size_t)e0.x * 16 + c]);
            float4 v1 = __ldg(&feat[(size_t)e1.x * 16 + c]);
            float4 v2 = __ldg(&feat[(size_t)e2.x * 16 + c]);
            float4 v3 = __ldg(&feat[(size_t)e3.x * 16 + c]);
            float w0 = __int_as_float(e0.y), w1 = __int_as_float(e1.y);
            float w2 = __int_as_float(e2.y), w3 = __int_as_float(e3.y);
            accA.x += w0 * v0.x + w1 * v1.x + w2 * v2.x + w3 * v3.x;
            accA.y += w0 * v0.y + w1 * v1.y + w2 * v2.y + w3 * v3.y;
            accA.z += w0 * v0.z + w1 * v1.z + w2 * v2.z + w3 * v3.z;
            accA.w += w0 * v0.w + w1 * v1.w + w2 * v2.w + w3 * v3.w;
        }
        for (; i < e; i++) {
            int2 ed = g_pedge[i];
            float w = __int_as_float(ed.y);
            float4 v = __ldg(&feat[(size_t)ed.x * 16 + c]);
            accA.x += w * v.x; accA.y += w * v.y; accA.z += w * v.z; accA.w += w * v.w;
        }
    }

    int sc = c ^ (swap << 3);
    float4 accB = make_float4(0.f, 0.f, 0.f, 0.f);
    {
        int b = g_noff[n], e = g_noff[n + 1];
        int i = b;
        for (; i + 4 <= e; i += 4) {
            int2 e0 = g_nedge[i + 0];
            int2 e1 = g_nedge[i + 1];
            int2 e2 = g_nedge[i + 2];
            int2 e3 = g_nedge[i + 3];
            float4 v0 = __ldg(&feat[(size_t)e0.x * 16 + sc]);
            float4 v1 = __ldg(&feat[(size_t)e1.x * 16 + sc]);
            float4 v2 = __ldg(&feat[(size_t)e2.x * 16 + sc]);
            float4 v3 = __ldg(&feat[(size_t)e3.x * 16 + sc]);
            float w0 = __int_as_float(e0.y), w1 = __int_as_float(e1.y);
            float w2 = __int_as_float(e2.y), w3 = __int_as_float(e3.y);
            accB.x += w0 * v0.x + w1 * v1.x + w2 * v2.x + w3 * v3.x;
            accB.y += w0 * v0.y + w1 * v1.y + w2 * v2.y + w3 * v3.y;
            accB.z += w0 * v0.z + w1 * v1.z + w2 * v2.z + w3 * v3.z;
            accB.w += w0 * v0.w + w1 * v1.w + w2 * v2.w + w3 * v3.w;
        }
        for (; i < e; i++) {
            int2 ed = g_nedge[i];
            float w = __int_as_float(ed.y);
            float4 v = __ldg(&feat[(size_t)ed.x * 16 + sc]);
            accB.x += w * v.x; accB.y += w * v.y; accB.z += w * v.z; accB.w += w * v.w;
        }
    }

    reinterpret_cast<float4*>(g_aggA)[n * 16 + c] = accA;
    reinterpret_cast<float4*>(g_aggB)[n * 16 + c] = accB;
}

// ---------------- layer 1: z = tanh([ap,x]@w1p+b1p | [an,x]@w1n+b1n) ---------
__global__ __launch_bounds__(128) void layer1_kernel(
    const float4* __restrict__ x4,
    const float* __restrict__ w1p, const float* __restrict__ b1p,
    const float* __restrict__ w1n, const float* __restrict__ b1n) {
    __shared__ float sWp[128 * 32];
    __shared__ float sWn[128 * 32];
    for (int i = threadIdx.x; i < 128 * 32; i += 128) {
        sWp[i] = w1p[i];
        sWn[i] = w1n[i];
    }
    __syncthreads();

    int n = blockIdx.x * 128 + threadIdx.x;
    if (n >= NN) return;

    float invp = 1.f / fmaxf(g_dpos[n], 1e-12f);
    float invn = 1.f / fmaxf(g_dneg[n], 1e-12f);

    float aP[32], aN[32];
#pragma unroll
    for (int j = 0; j < 32; j++) { aP[j] = b1p[j]; aN[j] = b1n[j]; }

    const float4* rA = reinterpret_cast<const float4*>(g_aggA) + n * 16;
    const float4* rB = reinterpret_cast<const float4*>(g_aggB) + n * 16;
    const float4* rX = x4 + n * 16;

#pragma unroll 1
    for (int k4 = 0; k4 < 16; k4++) {
        float4 a = rA[k4];
        float4 b = rB[k4];
        float4 xv = rX[k4];
        float av[4] = { a.x * invp, a.y * invp, a.z * invp, a.w * invp };
        float bv[4] = { b.x * invn, b.y * invn, b.z * invn, b.w * invn };
        float xe[4] = { xv.x, xv.y, xv.z, xv.w };
#pragma unroll
        for (int kk = 0; kk < 4; kk++) {
            int k = k4 * 4 + kk;
            const float4* wpA = reinterpret_cast<const float4*>(sWp + k * 32);
            const float4* wpX = reinterpret_cast<const float4*>(sWp + (64 + k) * 32);
            const float4* wnA = reinterpret_cast<const float4*>(sWn + k * 32);
            const float4* wnX = reinterpret_cast<const float4*>(sWn + (64 + k) * 32);
#pragma unroll
            for (int j4 = 0; j4 < 8; j4++) {
                float4 wp = wpA[j4];
                float4 wx = wpX[j4];
                float4 wn = wnA[j4];
                float4 wq = wnX[j4];
                aP[4 * j4 + 0] += av[kk] * wp.x + xe[kk] * wx.x;
                aP[4 * j4 + 1] += av[kk] * wp.y + xe[kk] * wx.y;
                aP[4 * j4 + 2] += av[kk] * wp.z + xe[kk] * wx.z;
                aP[4 * j4 + 3] += av[kk] * wp.w + xe[kk] * wx.w;
                aN[4 * j4 + 0] += bv[kk] * wn.x + xe[kk] * wq.x;
                aN[4 * j4 + 1] += bv[kk] * wn.y + xe[kk] * wq.y;
                aN[4 * j4 + 2] += bv[kk] * wn.z + xe[kk] * wq.z;
                aN[4 * j4 + 3] += bv[kk] * wn.w + xe[kk] * wq.w;
            }
        }
    }

    float4* zr = reinterpret_cast<float4*>(g_z + (size_t)n * 64);
#pragma unroll
    for (int j4 = 0; j4 < 8; j4++) {
        zr[j4] = make_float4(tanha(aP[4 * j4 + 0]), tanha(aP[4 * j4 + 1]),
                             tanha(aP[4 * j4 + 2]), tanha(aP[4 * j4 + 3]));
        zr[8 + j4] = make_float4(tanha(aN[4 * j4 + 0]), tanha(aN[4 * j4 + 1]),
                                 tanha(aN[4 * j4 + 2]), tanha(aN[4 * j4 + 3]));
    }
}

// ---------------- layer 2 ----------------------------------------------------
__global__ __launch_bounds__(128) void layer2_kernel(
    const float* __restrict__ w2p, const float* __restrict__ b2p,
    const float* __restrict__ w2n, const float* __restrict__ b2n) {
    __shared__ float sP[96 * 32];
    __shared__ float sN[96 * 32];
    for (int i = threadIdx.x; i < 96 * 32; i += 128) {
        sP[i] = w2p[i];
        sN[i] = w2n[i];
    }
    __syncthreads();

    int n = blockIdx.x * 128 + threadIdx.x;
    if (n >= NN) return;

    float invp = 1.f / fmaxf(g_dpos[n], 1e-12f);
    float invn = 1.f / fmaxf(g_dneg[n], 1e-12f);

    float aP[32], aN[32];
#pragma unroll
    for (int j = 0; j < 32; j++) { aP[j] = b2p[j]; aN[j] = b2n[j]; }

    const float4* rA = reinterpret_cast<const float4*>(g_aggA) + n * 16;
    const float4* rB = reinterpret_cast<const float4*>(g_aggB) + n * 16;
    const float4* rZ = reinterpret_cast<const float4*>(g_z) + n * 16;

#pragma unroll 1
    for (int k4 = 0; k4 < 8; k4++) {
        float4 A1 = rA[k4];
        float4 A3 = rA[8 + k4];
        float4 A2 = rB[k4];
        float4 A4 = rB[8 + k4];
        float4 zp = rZ[k4];
        float4 zn = rZ[8 + k4];
        float a1[4] = { A1.x * invp, A1.y * invp, A1.z * invp, A1.w * invp };
        float a3[4] = { A3.x * invp, A3.y * invp, A3.z * invp, A3.w * invp };
        float a2[4] = { A2.x * invn, A2.y * invn, A2.z * invn, A2.w * invn };
        float a4[4] = { A4.x * invn, A4.y * invn, A4.z * invn, A4.w * invn };
        float zpv[4] = { zp.x, zp.y, zp.z, zp.w };
        float znv[4] = { zn.x, zn.y, zn.z, zn.w };
#pragma unroll
        for (int kk = 0; kk < 4; kk++) {
            int k = k4 * 4 + kk;
            const float4* p0 = reinterpret_cast<const float4*>(sP + k * 32);
            const float4* p1 = reinterpret_cast<const float4*>(sP + (32 + k) * 32);
            const float4* p2 = reinterpret_cast<const float4*>(sP + (64 + k) * 32);
            const float4* q0 = reinterpret_cast<const float4*>(sN + k * 32);
            const float4* q1 = reinterpret_cast<const float4*>(sN + (32 + k) * 32);
            const float4* q2 = reinterpret_cast<const float4*>(sN + (64 + k) * 32);
#pragma unroll
            for (int j4 = 0; j4 < 8; j4++) {
                float4 w0 = p0[j4], w1 = p1[j4], w2 = p2[j4];
                aP[4 * j4 + 0] += a1[kk] * w0.x + a2[kk] * w1.x + zpv[kk] * w2.x;
                aP[4 * j4 + 1] += a1[kk] * w0.y + a2[kk] * w1.y + zpv[kk] * w2.y;
                aP[4 * j4 + 2] += a1[kk] * w0.z + a2[kk] * w1.z + zpv[kk] * w2.z;
                aP[4 * j4 + 3] += a1[kk] * w0.w + a2[kk] * w1.w + zpv[kk] * w2.w;
                float4 v0 = q0[j4], v1 = q1[j4], v2 = q2[j4];
                aN[4 * j4 + 0] += a3[kk] * v0.x + a4[kk] * v1.x + znv[kk] * v2.x;
                aN[4 * j4 + 1] += a3[kk] * v0.y + a4[kk] * v1.y + znv[kk] * v2.y;
                aN[4 * j4 + 2] += a3[kk] * v0.z + a4[kk] * v1.z + znv[kk] * v2.z;
                aN[4 * j4 + 3] += a3[kk] * v0.w + a4[kk] * v1.w + znv[kk] * v2.w;
            }
        }
    }

    float4* zr = reinterpret_cast<float4*>(g_z + (size_t)n * 64);
#pragma unroll
    for (int j4 = 0; j4 < 8; j4++) {
        zr[j4] = make_float4(tanha(aP[4 * j4 + 0]), tanha(aP[4 * j4 + 1]),
                             tanha(aP[4 * j4 + 2]), tanha(aP[4 * j4 + 3]));
        zr[8 + j4] = make_float4(tanha(aN[4 * j4 + 0]), tanha(aN[4 * j4 + 1]),
                                 tanha(aN[4 * j4 + 2]), tanha(aN[4 * j4 + 3]));
    }
}

// ---------------- layer 3: out = tanh(z2 @ wout + bout) ----------------------
__global__ __launch_bounds__(128) void layer3_kernel(
    const float* __restrict__ wout, const float* __restrict__ bout,
    float* __restrict__ out) {
    __shared__ float sO[64 * 64];
    for (int i = threadIdx.x; i < 64 * 64; i += 128) sO[i] = wout[i];
    __syncthreads();

    int n = blockIdx.x * 128 + threadIdx.x;
    if (n >= NN) return;

    float o[64];
#pragma unroll
    for (int j = 0; j < 64; j++) o[j] = bout[j];

    const float4* rz = reinterpret_cast<const float4*>(g_z) + n * 16;
#pragma unroll 1
    for (int k4 = 0; k4 < 16; k4++) {
        float4 zc = rz[k4];
        float zv[4] = { zc.x, zc.y, zc.z, zc.w };
#pragma unroll
        for (int kk = 0; kk < 4; kk++) {
            const float4* wr = reinterpret_cast<const float4*>(sO + (k4 * 4 + kk) * 64);
#pragma unroll
            for (int j4 = 0; j4 < 16; j4++) {
                float4 w = wr[j4];
                o[4 * j4 + 0] += zv[kk] * w.x;
                o[4 * j4 + 1] += zv[kk] * w.y;
                o[4 * j4 + 2] += zv[kk] * w.z;
                o[4 * j4 + 3] += zv[kk] * w.w;
            }
        }
    }

    float4* orow = reinterpret_cast<float4*>(out + (size_t)n * 64);
#pragma unroll
    for (int j4 = 0; j4 < 16; j4++) {
        orow[j4] = make_float4(tanha(o[4 * j4 + 0]), tanha(o[4 * j4 + 1]),
                               tanha(o[4 * j4 + 2]), tanha(o[4 * j4 + 3]));
    }
}

// ---------------- launch -----------------------------------------------------
extern "C" void kernel_launch(void* const* d_in, const int* in_sizes, int n_in,
                              void* d_out, int out_size) {
    const int*   pei  = (const int*)d_in[0];
    const int*   nei  = (const int*)d_in[1];
    const float* pw   = (const float*)d_in[2];
    const float* nw   = (const float*)d_in[3];
    const float* x    = (const float*)d_in[4];
    const float* w1p  = (const float*)d_in[5];
    const float* b1p  = (const float*)d_in[6];
    const float* w1n  = (const float*)d_in[7];
    const float* b1n  = (const float*)d_in[8];
    const float* w2p  = (const float*)d_in[9];
    const float* b2p  = (const float*)d_in[10];
    const float* w2n  = (const float*)d_in[11];
    const float* b2n  = (const float*)d_in[12];
    const float* wout = (const float*)d_in[13];
    const float* bout = (const float*)d_in[14];
    float* out = (float*)d_out;

    const int EB = (EP + EN + 255) / 256;
    const int GB = (NN * 16 + 255) / 256;
    const int LB = (NN + 127) / 128;

    // CSR build (shared by both layers)
    zero_cnt_kernel<<<(NN + 255) / 256, 256>>>();
    hist_kernel<<<EB, 256>>>(pei, nei, pw, nw);
    scan1_kernel<<<dim3(NBLK, 2), 1024>>>();
    scan3_kernel<<<dim3(NBLK, 2), 1024>>>();
    fill_kernel<<<EB, 256>>>(pei, nei, pw, nw);

    // Layer 1
    gather_kernel<<<GB, 256>>>((const float4*)x, 0, 0);
    layer1_kernel<<<LB, 128>>>((const float4*)x, w1p, b1p, w1n, b1n);

    // Layer 2 (neg side swaps zp/zn halves in the gather), then layer 3
    gather_kernel<<<GB, 256>>>((const float4*)x, 1, 1);
    layer2_kernel<<<LB, 128>>>(w2p, b2p, w2n, b2n);
    layer3_kernel<<<LB, 128>>>(wout, bout, out);

    (void)in_sizes; (void)n_in; (void)out_size;
}

// round 10
// speedup vs baseline: 1.2140x; 1.0294x over previous
#include <cuda_runtime.h>
#include <cstdint>

#define NN 100000
#define EP 1000000
#define EN 500000
#define NBLK ((NN + 1023) / 1024)   // 98

// ---------------- scratch (device globals: no allocations allowed) ----------
__device__ __align__(256) float g_aggA[NN * 64];   // pos-sourced aggregation sums
__device__ __align__(256) float g_aggB[NN * 64];   // neg-sourced aggregation sums
__device__ __align__(256) float g_z[NN * 64];      // layer1 output, then layer2 output
__device__ __align__(256) float g_dpos[NN];        // sum of pos weights per dst
__device__ __align__(256) float g_dneg[NN];        // sum of neg weights per dst
// CSR build
__device__ __align__(256) int  g_pcnt[NN];
__device__ __align__(256) int  g_ncnt[NN];
__device__ __align__(256) int  g_poff[NN + 1];
__device__ __align__(256) int  g_noff[NN + 1];
__device__ __align__(256) int  g_prank[EP];
__device__ __align__(256) int  g_nrank[EN];
__device__ __align__(256) int  g_blksum[2][NBLK];
__device__ __align__(256) int2 g_pedge[EP];        // (src, bitcast weight) in dst order
__device__ __align__(256) int2 g_nedge[EN];

// ---------------- helpers ----------------------------------------------------
__device__ __forceinline__ float tanha(float x) {
    float r;
    asm("tanh.approx.f32 %0, %1;" : "=f"(r) : "f"(x));
    return r;
}

// ---------------- CSR build --------------------------------------------------
__global__ void zero_cnt_kernel() {
    int i = blockIdx.x * blockDim.x + threadIdx.x;
    if (i < NN) {
        g_pcnt[i] = 0;
        g_ncnt[i] = 0;
    }
}

// Count edges per dst; the atomic's return value is this edge's rank within dst.
// (Weight sums are now computed in gather #1 — no float atomics here.)
__global__ void hist_kernel(const int* __restrict__ pei, const int* __restrict__ nei) {
    int t = blockIdx.x * blockDim.x + threadIdx.x;
    if (t < EP) {
        int d = pei[EP + t];
        g_prank[t] = atomicAdd(&g_pcnt[d], 1);
    } else if (t < EP + EN) {
        int e = t - EP;
        int d = nei[EN + e];
        g_nrank[e] = atomicAdd(&g_ncnt[d], 1);
    }
}

// Phase 1: per-block exclusive scan; block totals to g_blksum.
__global__ void scan1_kernel() {
    __shared__ int swsum[32];
    int arr = blockIdx.y;
    const int* cnt = arr ? g_ncnt : g_pcnt;
    int* off = arr ? g_noff : g_poff;
    int tid = threadIdx.x, lane = tid & 31, wid = tid >> 5;
    int i = blockIdx.x * 1024 + tid;
    int v = (i < NN) ? cnt[i] : 0;
    int val = v;
#pragma unroll
    for (int o = 1; o < 32; o <<= 1) {
        int t2 = __shfl_up_sync(0xFFFFFFFFu, val, o);
        if (lane >= o) val += t2;
    }
    if (lane == 31) swsum[wid] = val;
    __syncthreads();
    if (wid == 0) {
        int s = swsum[lane];
#pragma unroll
        for (int o = 1; o < 32; o <<= 1) {
            int t2 = __shfl_up_sync(0xFFFFFFFFu, s, o);
            if (lane >= o) s += t2;
        }
        swsum[lane] = s;
    }
    __syncthreads();
    int woff = wid ? swsum[wid - 1] : 0;
    int incl = val + woff;
    if (i < NN) off[i] = incl - v;
    if (tid == 1023) g_blksum[arr][blockIdx.x] = incl;
}

// Phase 2 (merged): each block reduces blksum[0..bx-1] and adds it.
__global__ void scan3_kernel() {
    __shared__ int s_pref;
    int arr = blockIdx.y;
    int* off = arr ? g_noff : g_poff;
    int bx = blockIdx.x;
    if (threadIdx.x < 32) {
        int lane = threadIdx.x;
        int acc = 0;
        for (int idx = lane; idx < bx; idx += 32) acc += g_blksum[arr][idx];
#pragma unroll
        for (int o = 16; o; o >>= 1) acc += __shfl_xor_sync(0xFFFFFFFFu, acc, o);
        if (lane == 0) s_pref = acc;
    }
    __syncthreads();
    int pref = s_pref;
    int i = bx * 1024 + threadIdx.x;
    if (i < NN) off[i] += pref;
    if (bx == NBLK - 1 && threadIdx.x == 0)
        off[NN] = pref + g_blksum[arr][NBLK - 1];
}

// Fill CSR edge arrays — no atomics (slot = off[dst] + precomputed rank).
__global__ void fill_kernel(const int* __restrict__ pei, const int* __restrict__ nei,
                            const float* __restrict__ pw, const float* __restrict__ nw) {
    int t = blockIdx.x * blockDim.x + threadIdx.x;
    if (t < EP) {
        int dst = pei[EP + t];
        g_pedge[g_poff[dst] + g_prank[t]] = make_int2(pei[t], __float_as_int(pw[t]));
    } else if (t < EP + EN) {
        int e = t - EP;
        int dst = nei[EN + e];
        g_nedge[g_noff[dst] + g_nrank[e]] = make_int2(nei[e], __float_as_int(nw[e]));
    }
}

// ---------------- CSR gather (pos + neg in one pass, 4-deep pipelined) -------
// 16 threads per node; thread c owns float4 chunk c of the 64-float row.
// dosum: on the first gather, thread c==0 also stores the per-node weight sums.
__global__ void gather_kernel(const float4* __restrict__ xfeat, int use_z, int swap,
                              int dosum) {
    int t = blockIdx.x * blockDim.x + threadIdx.x;
    int n = t >> 4;
    if (n >= NN) return;
    int c = t & 15;
    const float4* feat = use_z ? reinterpret_cast<const float4*>(g_z) : xfeat;

    float4 accA = make_float4(0.f, 0.f, 0.f, 0.f);
    float wsumA = 0.f;
    {
        int b = g_poff[n], e = g_poff[n + 1];
        int i = b;
        for (; i + 4 <= e; i += 4) {
            int2 e0 = g_pedge[i + 0];
            int2 e1 = g_pedge[i + 1];
            int2 e2 = g_pedge[i + 2];
            int2 e3 = g_pedge[i + 3];
            float4 v0 = __ldg(&feat[(size_t)e0.x * 16 + c]);
            float4 v1 = __ldg(&feat[(size_t)e1.x * 16 + c]);
            float4 v2 = __ldg(&feat[(size_t)e2.x * 16 + c]);
            float4 v3 = __ldg(&feat[(size_t)e3.x * 16 + c]);
            float w0 = __int_as_float(e0.y), w1 = __int_as_float(e1.y);
            float w2 = __int_as_float(e2.y), w3 = __int_as_float(e3.y);
            wsumA += w0 + w1 + w2 + w3;
            accA.x += w0 * v0.x + w1 * v1.x + w2 * v2.x + w3 * v3.x;
            accA.y += w0 * v0.y + w1 * v1.y + w2 * v2.y + w3 * v3.y;
            accA.z += w0 * v0.z + w1 * v1.z + w2 * v2.z + w3 * v3.z;
            accA.w += w0 * v0.w + w1 * v1.w + w2 * v2.w + w3 * v3.w;
        }
        for (; i < e; i++) {
            int2 ed = g_pedge[i];
            float w = __int_as_float(ed.y);
            float4 v = __ldg(&feat[(size_t)ed.x * 16 + c]);
            wsumA += w;
            accA.x += w * v.x; accA.y += w * v.y; accA.z += w * v.z; accA.w += w * v.w;
        }
    }

    int sc = c ^ (swap << 3);
    float4 accB = make_float4(0.f, 0.f, 0.f, 0.f);
    float wsumB = 0.f;
    {
        int b = g_noff[n], e = g_noff[n + 1];
        int i = b;
        for (; i + 4 <= e; i += 4) {
            int2 e0 = g_nedge[i + 0];
            int2 e1 = g_nedge[i + 1];
            int2 e2 = g_nedge[i + 2];
            int2 e3 = g_nedge[i + 3];
            float4 v0 = __ldg(&feat[(size_t)e0.x * 16 + sc]);
            float4 v1 = __ldg(&feat[(size_t)e1.x * 16 + sc]);
            float4 v2 = __ldg(&feat[(size_t)e2.x * 16 + sc]);
            float4 v3 = __ldg(&feat[(size_t)e3.x * 16 + sc]);
            float w0 = __int_as_float(e0.y), w1 = __int_as_float(e1.y);
            float w2 = __int_as_float(e2.y), w3 = __int_as_float(e3.y);
            wsumB += w0 + w1 + w2 + w3;
            accB.x += w0 * v0.x + w1 * v1.x + w2 * v2.x + w3 * v3.x;
            accB.y += w0 * v0.y + w1 * v1.y + w2 * v2.y + w3 * v3.y;
            accB.z += w0 * v0.z + w1 * v1.z + w2 * v2.z + w3 * v3.z;
            accB.w += w0 * v0.w + w1 * v1.w + w2 * v2.w + w3 * v3.w;
        }
        for (; i < e; i++) {
            int2 ed = g_nedge[i];
            float w = __int_as_float(ed.y);
            float4 v = __ldg(&feat[(size_t)ed.x * 16 + sc]);
            wsumB += w;
            accB.x += w * v.x; accB.y += w * v.y; accB.z += w * v.z; accB.w += w * v.w;
        }
    }

    reinterpret_cast<float4*>(g_aggA)[n * 16 + c] = accA;
    reinterpret_cast<float4*>(g_aggB)[n * 16 + c] = accB;
    if (dosum && c == 0) {
        g_dpos[n] = wsumA;
        g_dneg[n] = wsumB;
    }
}

// ---------------- layer 1: z = tanh([ap,x]@w1p+b1p | [an,x]@w1n+b1n) ---------
__global__ __launch_bounds__(128) void layer1_kernel(
    const float4* __restrict__ x4,
    const float* __restrict__ w1p, const float* __restrict__ b1p,
    const float* __restrict__ w1n, const float* __restrict__ b1n) {
    __shared__ float sWp[128 * 32];
    __shared__ float sWn[128 * 32];
    for (int i = threadIdx.x; i < 128 * 32; i += 128) {
        sWp[i] = w1p[i];
        sWn[i] = w1n[i];
    }
    __syncthreads();

    int n = blockIdx.x * 128 + threadIdx.x;
    if (n >= NN) return;

    float invp = 1.f / fmaxf(g_dpos[n], 1e-12f);
    float invn = 1.f / fmaxf(g_dneg[n], 1e-12f);

    float aP[32], aN[32];
#pragma unroll
    for (int j = 0; j < 32; j++) { aP[j] = b1p[j]; aN[j] = b1n[j]; }

    const float4* rA = reinterpret_cast<const float4*>(g_aggA) + n * 16;
    const float4* rB = reinterpret_cast<const float4*>(g_aggB) + n * 16;
    const float4* rX = x4 + n * 16;

#pragma unroll 1
    for (int k4 = 0; k4 < 16; k4++) {
        float4 a = rA[k4];
        float4 b = rB[k4];
        float4 xv = rX[k4];
        float av[4] = { a.x * invp, a.y * invp, a.z * invp, a.w * invp };
        float bv[4] = { b.x * invn, b.y * invn, b.z * invn, b.w * invn };
        float xe[4] = { xv.x, xv.y, xv.z, xv.w };
#pragma unroll
        for (int kk = 0; kk < 4; kk++) {
            int k = k4 * 4 + kk;
            const float4* wpA = reinterpret_cast<const float4*>(sWp + k * 32);
            const float4* wpX = reinterpret_cast<const float4*>(sWp + (64 + k) * 32);
            const float4* wnA = reinterpret_cast<const float4*>(sWn + k * 32);
            const float4* wnX = reinterpret_cast<const float4*>(sWn + (64 + k) * 32);
#pragma unroll
            for (int j4 = 0; j4 < 8; j4++) {
                float4 wp = wpA[j4];
                float4 wx = wpX[j4];
                float4 wn = wnA[j4];
                float4 wq = wnX[j4];
                aP[4 * j4 + 0] += av[kk] * wp.x + xe[kk] * wx.x;
                aP[4 * j4 + 1] += av[kk] * wp.y + xe[kk] * wx.y;
                aP[4 * j4 + 2] += av[kk] * wp.z + xe[kk] * wx.z;
                aP[4 * j4 + 3] += av[kk] * wp.w + xe[kk] * wx.w;
                aN[4 * j4 + 0] += bv[kk] * wn.x + xe[kk] * wq.x;
                aN[4 * j4 + 1] += bv[kk] * wn.y + xe[kk] * wq.y;
                aN[4 * j4 + 2] += bv[kk] * wn.z + xe[kk] * wq.z;
                aN[4 * j4 + 3] += bv[kk] * wn.w + xe[kk] * wq.w;
            }
        }
    }

    float4* zr = reinterpret_cast<float4*>(g_z + (size_t)n * 64);
#pragma unroll
    for (int j4 = 0; j4 < 8; j4++) {
        zr[j4] = make_float4(tanha(aP[4 * j4 + 0]), tanha(aP[4 * j4 + 1]),
                             tanha(aP[4 * j4 + 2]), tanha(aP[4 * j4 + 3]));
        zr[8 + j4] = make_float4(tanha(aN[4 * j4 + 0]), tanha(aN[4 * j4 + 1]),
                                 tanha(aN[4 * j4 + 2]), tanha(aN[4 * j4 + 3]));
    }
}

// ---------------- layer 2 ----------------------------------------------------
__global__ __launch_bounds__(128) void layer2_kernel(
    const float* __restrict__ w2p, const float* __restrict__ b2p,
    const float* __restrict__ w2n, const float* __restrict__ b2n) {
    __shared__ float sP[96 * 32];
    __shared__ float sN[96 * 32];
    for (int i = threadIdx.x; i < 96 * 32; i += 128) {
        sP[i] = w2p[i];
        sN[i] = w2n[i];
    }
    __syncthreads();

    int n = blockIdx.x * 128 + threadIdx.x;
    if (n >= NN) return;

    float invp = 1.f / fmaxf(g_dpos[n], 1e-12f);
    float invn = 1.f / fmaxf(g_dneg[n], 1e-12f);

    float aP[32], aN[32];
#pragma unroll
    for (int j = 0; j < 32; j++) { aP[j] = b2p[j]; aN[j] = b2n[j]; }

    const float4* rA = reinterpret_cast<const float4*>(g_aggA) + n * 16;
    const float4* rB = reinterpret_cast<const float4*>(g_aggB) + n * 16;
    const float4* rZ = reinterpret_cast<const float4*>(g_z) + n * 16;

#pragma unroll 1
    for (int k4 = 0; k4 < 8; k4++) {
        float4 A1 = rA[k4];
        float4 A3 = rA[8 + k4];
        float4 A2 = rB[k4];
        float4 A4 = rB[8 + k4];
        float4 zp = rZ[k4];
        float4 zn = rZ[8 + k4];
        float a1[4] = { A1.x * invp, A1.y * invp, A1.z * invp, A1.w * invp };
        float a3[4] = { A3.x * invp, A3.y * invp, A3.z * invp, A3.w * invp };
        float a2[4] = { A2.x * invn, A2.y * invn, A2.z * invn, A2.w * invn };
        float a4[4] = { A4.x * invn, A4.y * invn, A4.z * invn, A4.w * invn };
        float zpv[4] = { zp.x, zp.y, zp.z, zp.w };
        float znv[4] = { zn.x, zn.y, zn.z, zn.w };
#pragma unroll
        for (int kk = 0; kk < 4; kk++) {
            int k = k4 * 4 + kk;
            const float4* p0 = reinterpret_cast<const float4*>(sP + k * 32);
            const float4* p1 = reinterpret_cast<const float4*>(sP + (32 + k) * 32);
            const float4* p2 = reinterpret_cast<const float4*>(sP + (64 + k) * 32);
            const float4* q0 = reinterpret_cast<const float4*>(sN + k * 32);
            const float4* q1 = reinterpret_cast<const float4*>(sN + (32 + k) * 32);
            const float4* q2 = reinterpret_cast<const float4*>(sN + (64 + k) * 32);
#pragma unroll
            for (int j4 = 0; j4 < 8; j4++) {
                float4 w0 = p0[j4], w1 = p1[j4], w2 = p2[j4];
                aP[4 * j4 + 0] += a1[kk] * w0.x + a2[kk] * w1.x + zpv[kk] * w2.x;
                aP[4 * j4 + 1] += a1[kk] * w0.y + a2[kk] * w1.y + zpv[kk] * w2.y;
                aP[4 * j4 + 2] += a1[kk] * w0.z + a2[kk] * w1.z + zpv[kk] * w2.z;
                aP[4 * j4 + 3] += a1[kk] * w0.w + a2[kk] * w1.w + zpv[kk] * w2.w;
                float4 v0 = q0[j4], v1 = q1[j4], v2 = q2[j4];
                aN[4 * j4 + 0] += a3[kk] * v0.x + a4[kk] * v1.x + znv[kk] * v2.x;
                aN[4 * j4 + 1] += a3[kk] * v0.y + a4[kk] * v1.y + znv[kk] * v2.y;
                aN[4 * j4 + 2] += a3[kk] * v0.z + a4[kk] * v1.z + znv[kk] * v2.z;
                aN[4 * j4 + 3] += a3[kk] * v0.w + a4[kk] * v1.w + znv[kk] * v2.w;
            }
        }
    }

    float4* zr = reinterpret_cast<float4*>(g_z + (size_t)n * 64);
#pragma unroll
    for (int j4 = 0; j4 < 8; j4++) {
        zr[j4] = make_float4(tanha(aP[4 * j4 + 0]), tanha(aP[4 * j4 + 1]),
                             tanha(aP[4 * j4 + 2]), tanha(aP[4 * j4 + 3]));
        zr[8 + j4] = make_float4(tanha(aN[4 * j4 + 0]), tanha(aN[4 * j4 + 1]),
                                 tanha(aN[4 * j4 + 2]), tanha(aN[4 * j4 + 3]));
    }
}

// ---------------- layer 3: out = tanh(z2 @ wout + bout) ----------------------
__global__ __launch_bounds__(128) void layer3_kernel(
    const float* __restrict__ wout, const float* __restrict__ bout,
    float* __restrict__ out) {
    __shared__ float sO[64 * 64];
    for (int i = threadIdx.x; i < 64 * 64; i += 128) sO[i] = wout[i];
    __syncthreads();

    int n = blockIdx.x * 128 + threadIdx.x;
    if (n >= NN) return;

    float o[64];
#pragma unroll
    for (int j = 0; j < 64; j++) o[j] = bout[j];

    const float4* rz = reinterpret_cast<const float4*>(g_z) + n * 16;
#pragma unroll 1
    for (int k4 = 0; k4 < 16; k4++) {
        float4 zc = rz[k4];
        float zv[4] = { zc.x, zc.y, zc.z, zc.w };
#pragma unroll
        for (int kk = 0; kk < 4; kk++) {
            const float4* wr = reinterpret_cast<const float4*>(sO + (k4 * 4 + kk) * 64);
#pragma unroll
            for (int j4 = 0; j4 < 16; j4++) {
                float4 w = wr[j4];
                o[4 * j4 + 0] += zv[kk] * w.x;
                o[4 * j4 + 1] += zv[kk] * w.y;
                o[4 * j4 + 2] += zv[kk] * w.z;
                o[4 * j4 + 3] += zv[kk] * w.w;
            }
        }
    }

    float4* orow = reinterpret_cast<float4*>(out + (size_t)n * 64);
#pragma unroll
    for (int j4 = 0; j4 < 16; j4++) {
        orow[j4] = make_float4(tanha(o[4 * j4 + 0]), tanha(o[4 * j4 + 1]),
                               tanha(o[4 * j4 + 2]), tanha(o[4 * j4 + 3]));
    }
}

// ---------------- launch -----------------------------------------------------
extern "C" void kernel_launch(void* const* d_in, const int* in_sizes, int n_in,
                              void* d_out, int out_size) {
    const int*   pei  = (const int*)d_in[0];
    const int*   nei  = (const int*)d_in[1];
    const float* pw   = (const float*)d_in[2];
    const float* nw   = (const float*)d_in[3];
    const float* x    = (const float*)d_in[4];
    const float* w1p  = (const float*)d_in[5];
    const float* b1p  = (const float*)d_in[6];
    const float* w1n  = (const float*)d_in[7];
    const float* b1n  = (const float*)d_in[8];
    const float* w2p  = (const float*)d_in[9];
    const float* b2p  = (const float*)d_in[10];
    const float* w2n  = (const float*)d_in[11];
    const float* b2n  = (const float*)d_in[12];
    const float* wout = (const float*)d_in[13];
    const float* bout = (const float*)d_in[14];
    float* out = (float*)d_out;

    const int EB = (EP + EN + 255) / 256;
    const int GB = (NN * 16 + 255) / 256;
    const int LB = (NN + 127) / 128;

    // CSR build (shared by both layers)
    zero_cnt_kernel<<<(NN + 255) / 256, 256>>>();
    hist_kernel<<<EB, 256>>>(pei, nei);
    scan1_kernel<<<dim3(NBLK, 2), 1024>>>();
    scan3_kernel<<<dim3(NBLK, 2), 1024>>>();
    fill_kernel<<<EB, 256>>>(pei, nei, pw, nw);

    // Layer 1 (gather also computes the per-node weight sums)
    gather_kernel<<<GB, 256>>>((const float4*)x, 0, 0, 1);
    layer1_kernel<<<LB, 128>>>((const float4*)x, w1p, b1p, w1n, b1n);

    // Layer 2 (neg side swaps zp/zn halves in the gather), then layer 3
    gather_kernel<<<GB, 256>>>((const float4*)x, 1, 1, 0);
    layer2_kernel<<<LB, 128>>>(w2p, b2p, w2n, b2n);
    layer3_kernel<<<LB, 128>>>(wout, bout, out);

    (void)in_sizes; (void)n_in; (void)out_size;
}

// round 11
// speedup vs baseline: 1.2291x; 1.0124x over previous
#include <cuda_runtime.h>
#include <cuda_fp16.h>
#include <cstdint>

#define NN 100000
#define EP 1000000
#define EN 500000
#define NBLK ((NN + 1023) / 1024)   // 98

// ---------------- scratch (device globals: no allocations allowed) ----------
__device__ __align__(256) float  g_aggA[NN * 64];  // agg sums; layer2 reuses as z2
__device__ __align__(256) float  g_aggB[NN * 64];
__device__ __align__(256) __half g_xh[NN * 64];    // fp16 copy of x
__device__ __align__(256) __half g_zh[NN * 64];    // fp16 layer1 output
__device__ __align__(256) float  g_dpos[NN];
__device__ __align__(256) float  g_dneg[NN];
// CSR build
__device__ __align__(256) int  g_pcnt[NN];
__device__ __align__(256) int  g_ncnt[NN];
__device__ __align__(256) int  g_poff[NN + 1];
__device__ __align__(256) int  g_noff[NN + 1];
__device__ __align__(256) int  g_prank[EP];
__device__ __align__(256) int  g_nrank[EN];
__device__ __align__(256) int  g_blksum[2][NBLK];
__device__ __align__(256) int2 g_pedge[EP];        // (src, bitcast weight) in dst order
__device__ __align__(256) int2 g_nedge[EN];

// ---------------- helpers ----------------------------------------------------
__device__ __forceinline__ float tanha(float x) {
    float r;
    asm("tanh.approx.f32 %0, %1;" : "=f"(r) : "f"(x));
    return r;
}

// ---------------- x -> fp16 --------------------------------------------------
__global__ void convx_kernel(const float4* __restrict__ x4) {
    int i = blockIdx.x * blockDim.x + threadIdx.x;
    if (i >= NN * 16) return;
    float4 v = x4[i];
    __half2 h0 = __floats2half2_rn(v.x, v.y);
    __half2 h1 = __floats2half2_rn(v.z, v.w);
    uint2 u;
    u.x = *reinterpret_cast<const unsigned*>(&h0);
    u.y = *reinterpret_cast<const unsigned*>(&h1);
    reinterpret_cast<uint2*>(g_xh)[i] = u;
}

// ---------------- CSR build --------------------------------------------------
__global__ void zero_cnt_kernel() {
    int i = blockIdx.x * blockDim.x + threadIdx.x;
    if (i < NN) {
        g_pcnt[i] = 0;
        g_ncnt[i] = 0;
    }
}

__global__ void hist_kernel(const int* __restrict__ pei, const int* __restrict__ nei) {
    int t = blockIdx.x * blockDim.x + threadIdx.x;
    if (t < EP) {
        int d = pei[EP + t];
        g_prank[t] = atomicAdd(&g_pcnt[d], 1);
    } else if (t < EP + EN) {
        int e = t - EP;
        int d = nei[EN + e];
        g_nrank[e] = atomicAdd(&g_ncnt[d], 1);
    }
}

// Phase 1: per-block exclusive scan; block totals to g_blksum.
__global__ void scan1_kernel() {
    __shared__ int swsum[32];
    int arr = blockIdx.y;
    const int* cnt = arr ? g_ncnt : g_pcnt;
    int* off = arr ? g_noff : g_poff;
    int tid = threadIdx.x, lane = tid & 31, wid = tid >> 5;
    int i = blockIdx.x * 1024 + tid;
    int v = (i < NN) ? cnt[i] : 0;
    int val = v;
#pragma unroll
    for (int o = 1; o < 32; o <<= 1) {
        int t2 = __shfl_up_sync(0xFFFFFFFFu, val, o);
        if (lane >= o) val += t2;
    }
    if (lane == 31) swsum[wid] = val;
    __syncthreads();
    if (wid == 0) {
        int s = swsum[lane];
#pragma unroll
        for (int o = 1; o < 32; o <<= 1) {
            int t2 = __shfl_up_sync(0xFFFFFFFFu, s, o);
            if (lane >= o) s += t2;
        }
        swsum[lane] = s;
    }
    __syncthreads();
    int woff = wid ? swsum[wid - 1] : 0;
    int incl = val + woff;
    if (i < NN) off[i] = incl - v;
    if (tid == 1023) g_blksum[arr][blockIdx.x] = incl;
}

// Phase 2 (merged): each block reduces blksum[0..bx-1] and adds it.
__global__ void scan3_kernel() {
    __shared__ int s_pref;
    int arr = blockIdx.y;
    int* off = arr ? g_noff : g_poff;
    int bx = blockIdx.x;
    if (threadIdx.x < 32) {
        int lane = threadIdx.x;
        int acc = 0;
        for (int idx = lane; idx < bx; idx += 32) acc += g_blksum[arr][idx];
#pragma unroll
        for (int o = 16; o; o >>= 1) acc += __shfl_xor_sync(0xFFFFFFFFu, acc, o);
        if (lane == 0) s_pref = acc;
    }
    __syncthreads();
    int pref = s_pref;
    int i = bx * 1024 + threadIdx.x;
    if (i < NN) off[i] += pref;
    if (bx == NBLK - 1 && threadIdx.x == 0)
        off[NN] = pref + g_blksum[arr][NBLK - 1];
}

// Fill CSR edge arrays — no atomics (slot = off[dst] + precomputed rank).
__global__ void fill_kernel(const int* __restrict__ pei, const int* __restrict__ nei,
                            const float* __restrict__ pw, const float* __restrict__ nw) {
    int t = blockIdx.x * blockDim.x + threadIdx.x;
    if (t < EP) {
        int dst = pei[EP + t];
        g_pedge[g_poff[dst] + g_prank[t]] = make_int2(pei[t], __float_as_int(pw[t]));
    } else if (t < EP + EN) {
        int e = t - EP;
        int dst = nei[EN + e];
        g_nedge[g_noff[dst] + g_nrank[e]] = make_int2(nei[e], __float_as_int(nw[e]));
    }
}

// ---------------- CSR gather over fp16 features ------------------------------
// 16 threads per node; thread c owns 4 halfs (8 B) of the 64-half row.
// use_z: 0 -> g_xh, 1 -> g_zh.  swap: neg side reads chunk c^8.
// dosum: thread c==0 stores per-node weight sums (first gather only).
__device__ __forceinline__ void h4acc(uint2 r, float w, float4& acc) {
    __half2 ha = *reinterpret_cast<__half2*>(&r.x);
    __half2 hb = *reinterpret_cast<__half2*>(&r.y);
    float2 fa = __half22float2(ha);
    float2 fb = __half22float2(hb);
    acc.x += w * fa.x; acc.y += w * fa.y;
    acc.z += w * fb.x; acc.w += w * fb.y;
}

__global__ void gather_kernel(int use_z, int swap, int dosum) {
    int t = blockIdx.x * blockDim.x + threadIdx.x;
    int n = t >> 4;
    if (n >= NN) return;
    int c = t & 15;
    const uint2* feat = use_z ? reinterpret_cast<const uint2*>(g_zh)
                              : reinterpret_cast<const uint2*>(g_xh);

    float4 accA = make_float4(0.f, 0.f, 0.f, 0.f);
    float wsumA = 0.f;
    {
        int b = g_poff[n], e = g_poff[n + 1];
        int i = b;
        for (; i + 4 <= e; i += 4) {
            int2 e0 = g_pedge[i + 0];
            int2 e1 = g_pedge[i + 1];
            int2 e2 = g_pedge[i + 2];
            int2 e3 = g_pedge[i + 3];
            uint2 r0 = __ldg(&feat[(size_t)e0.x * 16 + c]);
            uint2 r1 = __ldg(&feat[(size_t)e1.x * 16 + c]);
            uint2 r2 = __ldg(&feat[(size_t)e2.x * 16 + c]);
            uint2 r3 = __ldg(&feat[(size_t)e3.x * 16 + c]);
            float w0 = __int_as_float(e0.y), w1 = __int_as_float(e1.y);
            float w2 = __int_as_float(e2.y), w3 = __int_as_float(e3.y);
            wsumA += w0 + w1 + w2 + w3;
            h4acc(r0, w0, accA);
            h4acc(r1, w1, accA);
            h4acc(r2, w2, accA);
            h4acc(r3, w3, accA);
        }
        for (; i < e; i++) {
            int2 ed = g_pedge[i];
            float w = __int_as_float(ed.y);
            uint2 r = __ldg(&feat[(size_t)ed.x * 16 + c]);
            wsumA += w;
            h4acc(r, w, accA);
        }
    }

    int sc = c ^ (swap << 3);
    float4 accB = make_float4(0.f, 0.f, 0.f, 0.f);
    float wsumB = 0.f;
    {
        int b = g_noff[n], e = g_noff[n + 1];
        int i = b;
        for (; i + 4 <= e; i += 4) {
            int2 e0 = g_nedge[i + 0];
            int2 e1 = g_nedge[i + 1];
            int2 e2 = g_nedge[i + 2];
            int2 e3 = g_nedge[i + 3];
            uint2 r0 = __ldg(&feat[(size_t)e0.x * 16 + sc]);
            uint2 r1 = __ldg(&feat[(size_t)e1.x * 16 + sc]);
            uint2 r2 = __ldg(&feat[(size_t)e2.x * 16 + sc]);
            uint2 r3 = __ldg(&feat[(size_t)e3.x * 16 + sc]);
            float w0 = __int_as_float(e0.y), w1 = __int_as_float(e1.y);
            float w2 = __int_as_float(e2.y), w3 = __int_as_float(e3.y);
            wsumB += w0 + w1 + w2 + w3;
            h4acc(r0, w0, accB);
            h4acc(r1, w1, accB);
            h4acc(r2, w2, accB);
            h4acc(r3, w3, accB);
        }
        for (; i < e; i++) {
            int2 ed = g_nedge[i];
            float w = __int_as_float(ed.y);
            uint2 r = __ldg(&feat[(size_t)ed.x * 16 + sc]);
            wsumB += w;
            h4acc(r, w, accB);
        }
    }

    reinterpret_cast<float4*>(g_aggA)[n * 16 + c] = accA;
    reinterpret_cast<float4*>(g_aggB)[n * 16 + c] = accB;
    if (dosum && c == 0) {
        g_dpos[n] = wsumA;
        g_dneg[n] = wsumB;
    }
}

// ---------------- layer 1: z = tanh([ap,x]@w1p+b1p | [an,x]@w1n+b1n) ---------
// Writes z as fp16 into g_zh.
__global__ __launch_bounds__(128) void layer1_kernel(
    const float4* __restrict__ x4,
    const float* __restrict__ w1p, const float* __restrict__ b1p,
    const float* __restrict__ w1n, const float* __restrict__ b1n) {
    __shared__ float sWp[128 * 32];
    __shared__ float sWn[128 * 32];
    for (int i = threadIdx.x; i < 128 * 32; i += 128) {
        sWp[i] = w1p[i];
        sWn[i] = w1n[i];
    }
    __syncthreads();

    int n = blockIdx.x * 128 + threadIdx.x;
    if (n >= NN) return;

    float invp = 1.f / fmaxf(g_dpos[n], 1e-12f);
    float invn = 1.f / fmaxf(g_dneg[n], 1e-12f);

    float aP[32], aN[32];
#pragma unroll
    for (int j = 0; j < 32; j++) { aP[j] = b1p[j]; aN[j] = b1n[j]; }

    const float4* rA = reinterpret_cast<const float4*>(g_aggA) + n * 16;
    const float4* rB = reinterpret_cast<const float4*>(g_aggB) + n * 16;
    const float4* rX = x4 + n * 16;

#pragma unroll 1
    for (int k4 = 0; k4 < 16; k4++) {
        float4 a = rA[k4];
        float4 b = rB[k4];
        float4 xv = rX[k4];
        float av[4] = { a.x * invp, a.y * invp, a.z * invp, a.w * invp };
        float bv[4] = { b.x * invn, b.y * invn, b.z * invn, b.w * invn };
        float xe[4] = { xv.x, xv.y, xv.z, xv.w };
#pragma unroll
        for (int kk = 0; kk < 4; kk++) {
            int k = k4 * 4 + kk;
            const float4* wpA = reinterpret_cast<const float4*>(sWp + k * 32);
            const float4* wpX = reinterpret_cast<const float4*>(sWp + (64 + k) * 32);
            const float4* wnA = reinterpret_cast<const float4*>(sWn + k * 32);
            const float4* wnX = reinterpret_cast<const float4*>(sWn + (64 + k) * 32);
#pragma unroll
            for (int j4 = 0; j4 < 8; j4++) {
                float4 wp = wpA[j4];
                float4 wx = wpX[j4];
                float4 wn = wnA[j4];
                float4 wq = wnX[j4];
                aP[4 * j4 + 0] += av[kk] * wp.x + xe[kk] * wx.x;
                aP[4 * j4 + 1] += av[kk] * wp.y + xe[kk] * wx.y;
                aP[4 * j4 + 2] += av[kk] * wp.z + xe[kk] * wx.z;
                aP[4 * j4 + 3] += av[kk] * wp.w + xe[kk] * wx.w;
                aN[4 * j4 + 0] += bv[kk] * wn.x + xe[kk] * wq.x;
                aN[4 * j4 + 1] += bv[kk] * wn.y + xe[kk] * wq.y;
                aN[4 * j4 + 2] += bv[kk] * wn.z + xe[kk] * wq.z;
                aN[4 * j4 + 3] += bv[kk] * wn.w + xe[kk] * wq.w;
            }
        }
    }

    // z row = [zp(32) | zn(32)] halfs
    __half2* zr = reinterpret_cast<__half2*>(g_zh + (size_t)n * 64);
#pragma unroll
    for (int t2 = 0; t2 < 16; t2++) {
        zr[t2] = __floats2half2_rn(tanha(aP[2 * t2]), tanha(aP[2 * t2 + 1]));
        zr[16 + t2] = __floats2half2_rn(tanha(aN[2 * t2]), tanha(aN[2 * t2 + 1]));
    }
}

// ---------------- layer 2 ----------------------------------------------------
// Reads z fp16; writes z2 fp32 in-place into g_aggA (row-private).
__global__ __launch_bounds__(128) void layer2_kernel(
    const float* __restrict__ w2p, const float* __restrict__ b2p,
    const float* __restrict__ w2n, const float* __restrict__ b2n) {
    __shared__ float sP[96 * 32];
    __shared__ float sN[96 * 32];
    for (int i = threadIdx.x; i < 96 * 32; i += 128) {
        sP[i] = w2p[i];
        sN[i] = w2n[i];
    }
    __syncthreads();

    int n = blockIdx.x * 128 + threadIdx.x;
    if (n >= NN) return;

    float invp = 1.f / fmaxf(g_dpos[n], 1e-12f);
    float invn = 1.f / fmaxf(g_dneg[n], 1e-12f);

    float aP[32], aN[32];
#pragma unroll
    for (int j = 0; j < 32; j++) { aP[j] = b2p[j]; aN[j] = b2n[j]; }

    const float4* rA = reinterpret_cast<const float4*>(g_aggA) + n * 16;
    const float4* rB = reinterpret_cast<const float4*>(g_aggB) + n * 16;
    const uint2*  rZ = reinterpret_cast<const uint2*>(g_zh) + n * 16;

#pragma unroll 1
    for (int k4 = 0; k4 < 8; k4++) {
        float4 A1 = rA[k4];
        float4 A3 = rA[8 + k4];
        float4 A2 = rB[k4];
        float4 A4 = rB[8 + k4];
        uint2 zpu = rZ[k4];
        uint2 znu = rZ[8 + k4];
        float2 zp0 = __half22float2(*reinterpret_cast<__half2*>(&zpu.x));
        float2 zp1 = __half22float2(*reinterpret_cast<__half2*>(&zpu.y));
        float2 zn0 = __half22float2(*reinterpret_cast<__half2*>(&znu.x));
        float2 zn1 = __half22float2(*reinterpret_cast<__half2*>(&znu.y));
        float a1[4] = { A1.x * invp, A1.y * invp, A1.z * invp, A1.w * invp };
        float a3[4] = { A3.x * invp, A3.y * invp, A3.z * invp, A3.w * invp };
        float a2[4] = { A2.x * invn, A2.y * invn, A2.z * invn, A2.w * invn };
        float a4[4] = { A4.x * invn, A4.y * invn, A4.z * invn, A4.w * invn };
        float zpv[4] = { zp0.x, zp0.y, zp1.x, zp1.y };
        float znv[4] = { zn0.x, zn0.y, zn1.x, zn1.y };
#pragma unroll
        for (int kk = 0; kk < 4; kk++) {
            int k = k4 * 4 + kk;
            const float4* p0 = reinterpret_cast<const float4*>(sP + k * 32);
            const float4* p1 = reinterpret_cast<const float4*>(sP + (32 + k) * 32);
            const float4* p2 = reinterpret_cast<const float4*>(sP + (64 + k) * 32);
            const float4* q0 = reinterpret_cast<const float4*>(sN + k * 32);
            const float4* q1 = reinterpret_cast<const float4*>(sN + (32 + k) * 32);
            const float4* q2 = reinterpret_cast<const float4*>(sN + (64 + k) * 32);
#pragma unroll
            for (int j4 = 0; j4 < 8; j4++) {
                float4 w0 = p0[j4], w1 = p1[j4], w2 = p2[j4];
                aP[4 * j4 + 0] += a1[kk] * w0.x + a2[kk] * w1.x + zpv[kk] * w2.x;
                aP[4 * j4 + 1] += a1[kk] * w0.y + a2[kk] * w1.y + zpv[kk] * w2.y;
                aP[4 * j4 + 2] += a1[kk] * w0.z + a2[kk] * w1.z + zpv[kk] * w2.z;
                aP[4 * j4 + 3] += a1[kk] * w0.w + a2[kk] * w1.w + zpv[kk] * w2.w;
                float4 v0 = q0[j4], v1 = q1[j4], v2 = q2[j4];
                aN[4 * j4 + 0] += a3[kk] * v0.x + a4[kk] * v1.x + znv[kk] * v2.x;
                aN[4 * j4 + 1] += a3[kk] * v0.y + a4[kk] * v1.y + znv[kk] * v2.y;
                aN[4 * j4 + 2] += a3[kk] * v0.z + a4[kk] * v1.z + znv[kk] * v2.z;
                aN[4 * j4 + 3] += a3[kk] * v0.w + a4[kk] * v1.w + znv[kk] * v2.w;
            }
        }
    }

    // z2 (fp32) in-place into g_aggA row n (this thread's private row)
    float4* zr = reinterpret_cast<float4*>(g_aggA) + n * 16;
#pragma unroll
    for (int j4 = 0; j4 < 8; j4++) {
        zr[j4] = make_float4(tanha(aP[4 * j4 + 0]), tanha(aP[4 * j4 + 1]),
                             tanha(aP[4 * j4 + 2]), tanha(aP[4 * j4 + 3]));
        zr[8 + j4] = make_float4(tanha(aN[4 * j4 + 0]), tanha(aN[4 * j4 + 1]),
                                 tanha(aN[4 * j4 + 2]), tanha(aN[4 * j4 + 3]));
    }
}

// ---------------- layer 3: out = tanh(z2 @ wout + bout) ----------------------
__global__ __launch_bounds__(128) void layer3_kernel(
    const float* __restrict__ wout, const float* __restrict__ bout,
    float* __restrict__ out) {
    __shared__ float sO[64 * 64];
    for (int i = threadIdx.x; i < 64 * 64; i += 128) sO[i] = wout[i];
    __syncthreads();

    int n = blockIdx.x * 128 + threadIdx.x;
    if (n >= NN) return;

    float o[64];
#pragma unroll
    for (int j = 0; j < 64; j++) o[j] = bout[j];

    const float4* rz = reinterpret_cast<const float4*>(g_aggA) + n * 16;
#pragma unroll 1
    for (int k4 = 0; k4 < 16; k4++) {
        float4 zc = rz[k4];
        float zv[4] = { zc.x, zc.y, zc.z, zc.w };
#pragma unroll
        for (int kk = 0; kk < 4; kk++) {
            const float4* wr = reinterpret_cast<const float4*>(sO + (k4 * 4 + kk) * 64);
#pragma unroll
            for (int j4 = 0; j4 < 16; j4++) {
                float4 w = wr[j4];
                o[4 * j4 + 0] += zv[kk] * w.x;
                o[4 * j4 + 1] += zv[kk] * w.y;
                o[4 * j4 + 2] += zv[kk] * w.z;
                o[4 * j4 + 3] += zv[kk] * w.w;
            }
        }
    }

    float4* orow = reinterpret_cast<float4*>(out + (size_t)n * 64);
#pragma unroll
    for (int j4 = 0; j4 < 16; j4++) {
        orow[j4] = make_float4(tanha(o[4 * j4 + 0]), tanha(o[4 * j4 + 1]),
                               tanha(o[4 * j4 + 2]), tanha(o[4 * j4 + 3]));
    }
}

// ---------------- launch -----------------------------------------------------
extern "C" void kernel_launch(void* const* d_in, const int* in_sizes, int n_in,
                              void* d_out, int out_size) {
    const int*   pei  = (const int*)d_in[0];
    const int*   nei  = (const int*)d_in[1];
    const float* pw   = (const float*)d_in[2];
    const float* nw   = (const float*)d_in[3];
    const float* x    = (const float*)d_in[4];
    const float* w1p  = (const float*)d_in[5];
    const float* b1p  = (const float*)d_in[6];
    const float* w1n  = (const float*)d_in[7];
    const float* b1n  = (const float*)d_in[8];
    const float* w2p  = (const float*)d_in[9];
    const float* b2p  = (const float*)d_in[10];
    const float* w2n  = (const float*)d_in[11];
    const float* b2n  = (const float*)d_in[12];
    const float* wout = (const float*)d_in[13];
    const float* bout = (const float*)d_in[14];
    float* out = (float*)d_out;

    const int EB = (EP + EN + 255) / 256;
    const int GB = (NN * 16 + 255) / 256;
    const int LB = (NN + 127) / 128;

    // fp16 feature table + CSR build
    convx_kernel<<<(NN * 16 + 255) / 256, 256>>>((const float4*)x);
    zero_cnt_kernel<<<(NN + 255) / 256, 256>>>();
    hist_kernel<<<EB, 256>>>(pei, nei);
    scan1_kernel<<<dim3(NBLK, 2), 1024>>>();
    scan3_kernel<<<dim3(NBLK, 2), 1024>>>();
    fill_kernel<<<EB, 256>>>(pei, nei, pw, nw);

    // Layer 1 (gather also computes the per-node weight sums)
    gather_kernel<<<GB, 256>>>(0, 0, 1);
    layer1_kernel<<<LB, 128>>>((const float4*)x, w1p, b1p, w1n, b1n);

    // Layer 2 (neg side swaps zp/zn halves in the gather), then layer 3
    gather_kernel<<<GB, 256>>>(1, 1, 0);
    layer2_kernel<<<LB, 128>>>(w2p, b2p, w2n, b2n);
    layer3_kernel<<<LB, 128>>>(wout, bout, out);

    (void)in_sizes; (void)n_in; (void)out_size;
}